// round 14
// baseline (speedup 1.0000x reference)
#include <cuda_runtime.h>
#include <cuda_bf16.h>
#include <cstdint>
#include <cstddef>

#define MAXN 100000
#define MAXE 640000
#define DD   128

// ---------------- scratch (static device globals; no allocation) ------------
__device__ int   g_deg[MAXN];
__device__ int   g_cursor[MAXN];
__device__ int   g_off[MAXN + 1];
__device__ int   g_esrc[MAXE];
__device__ float g_invdeg[MAXN];
__device__ __nv_bfloat16 g_wthi[4 * 128 * 256];      // weights [mat][n][k], bf16 hi
__device__ __nv_bfloat16 g_wtlo[4 * 128 * 256];      // weights [mat][n][k], bf16 lo
// bf16 hi/lo planes:
__device__ __nv_bfloat16 g_px[(size_t)2 * MAXN * 256];   // x planes; later reused as h-pong (pitch 128)
__device__ __nv_bfloat16 g_ph[(size_t)2 * MAXN * 128];   // h planes ping
__device__ __nv_bfloat16 g_pagg[(size_t)2 * MAXN * 128]; // agg planes

// ---------------- helpers ---------------------------------------------------
__device__ __forceinline__ uint32_t smem_to_u32(const void* p) {
    uint32_t a;
    asm("{ .reg .u64 t; cvta.to.shared.u64 t, %1; cvt.u32.u64 %0, t; }" : "=r"(a) : "l"(p));
    return a;
}
#define SWZ(o) ((o) ^ (((o) >> 3) & 0x70))

__device__ __forceinline__ uint32_t cvt2(float a, float b, uint32_t& lo_out) {
    __nv_bfloat16 ha = __float2bfloat16(a), hb = __float2bfloat16(b);
    __nv_bfloat16 la = __float2bfloat16(a - __bfloat162float(ha));
    __nv_bfloat16 lb = __float2bfloat16(b - __bfloat162float(hb));
    lo_out = (uint32_t)__bfloat16_as_ushort(la) | ((uint32_t)__bfloat16_as_ushort(lb) << 16);
    return (uint32_t)__bfloat16_as_ushort(ha) | ((uint32_t)__bfloat16_as_ushort(hb) << 16);
}
__device__ __forceinline__ float2 bf2f(uint32_t u) {
    __nv_bfloat162 b;
    *reinterpret_cast<uint32_t*>(&b) = u;
    return __bfloat1622float2(b);
}
__device__ __forceinline__ void ldsm4(uint32_t* r, uint32_t addr) {
    asm volatile("ldmatrix.sync.aligned.m8n8.x4.shared.b16 {%0,%1,%2,%3}, [%4];"
                 : "=r"(r[0]), "=r"(r[1]), "=r"(r[2]), "=r"(r[3]) : "r"(addr));
}
__device__ __forceinline__ void mma16816(float* d, const uint32_t* a,
                                         uint32_t b0, uint32_t b1) {
    asm volatile(
        "mma.sync.aligned.m16n8k16.row.col.f32.bf16.bf16.f32 "
        "{%0,%1,%2,%3}, {%4,%5,%6,%7}, {%8,%9}, {%0,%1,%2,%3};"
        : "+f"(d[0]), "+f"(d[1]), "+f"(d[2]), "+f"(d[3])
        : "r"(a[0]), "r"(a[1]), "r"(a[2]), "r"(a[3]), "r"(b0), "r"(b1));
}
__device__ __forceinline__ void cp16(uint32_t dst, const void* src, int sz) {
    asm volatile("cp.async.cg.shared.global [%0], [%1], 16, %2;"
                 :: "r"(dst), "l"(src), "r"(sz));
}

// -------- block-partitioned prologue: x split | degree count | weight prep --
// g_deg pre-zeroed via cudaMemsetAsync. Each block runs exactly one path.
__global__ void k_pro(const float* __restrict__ x, const int* __restrict__ dst,
                      const float* __restrict__ W_in, const float* __restrict__ Wl,
                      const float* __restrict__ Wr,
                      int nf4, int E, int nbA, int nbB) {
    int b = blockIdx.x;
    if (b < nbA) {
        int u = b * 256 + threadIdx.x;
        if (u < nf4) {
            float4 f = ((const float4*)x)[u];
            uint32_t lo0, lo1;
            uint32_t hi0 = cvt2(f.x, f.y, lo0);
            uint32_t hi1 = cvt2(f.z, f.w, lo1);
            ((uint2*)g_px)[u] = make_uint2(hi0, hi1);
            ((uint2*)(g_px + (size_t)MAXN * 256))[u] = make_uint2(lo0, lo1);
        }
    } else if (b < nbA + nbB) {
        int e = (b - nbA) * 256 + threadIdx.x;
        if (e < E) atomicAdd(&g_deg[dst[e]], 1);
    } else {
        int u = (b - nbA - nbB) * 256 + threadIdx.x;
        if (u < 4 * 128 * 256) {
            int m = u >> 15;
            int n = (u >> 8) & 127;
            int k = u & 255;
            float v;
            if (m == 0) v = W_in[(size_t)k * 128 + n];
            else {
                int l = m - 1;
                v = (k < 128) ? Wl[((size_t)l * 128 + k) * 128 + n]
                              : Wr[((size_t)l * 128 + (k - 128)) * 128 + n];
            }
            __nv_bfloat16 hi = __float2bfloat16(v);
            g_wthi[u] = hi;
            g_wtlo[u] = __float2bfloat16(v - __bfloat162float(hi));
        }
    }
}

// ---------------- CSR fill (needs scan result) ------------------------------
__global__ void k_fill(const int* __restrict__ src, const int* __restrict__ dst, int E) {
    int e = blockIdx.x * blockDim.x + threadIdx.x;
    if (e < E) {
        int d = dst[e];
        int p = atomicAdd(&g_cursor[d], 1);
        g_esrc[g_off[d] + p] = src[e];
    }
}

// -------- mean aggregation: gather from h planes -> agg planes --------------
// 16 lanes handle hi plane, 16 handle lo plane; one 16B load per lane-edge.
__global__ void k_gather(const __nv_bfloat16* __restrict__ HHI,
                         const __nv_bfloat16* __restrict__ HLO, int N) {
    int gtid = blockIdx.x * blockDim.x + threadIdx.x;
    int node = gtid >> 5;
    int lane = gtid & 31;
    if (node >= N) return;
    int sub = lane & 15;                 // 8-dim group
    const __nv_bfloat16* P = (lane < 16) ? HHI : HLO;
    int beg = g_off[node], end = g_off[node + 1];
    float s0 = 0.f, s1 = 0.f, s2 = 0.f, s3 = 0.f,
          s4 = 0.f, s5 = 0.f, s6 = 0.f, s7 = 0.f;
    int e = beg;
    for (; e + 1 < end; e += 2) {
        int sA = g_esrc[e], sB = g_esrc[e + 1];
        uint4 vA = *(const uint4*)(P + (size_t)sA * 128 + sub * 8);
        uint4 vB = *(const uint4*)(P + (size_t)sB * 128 + sub * 8);
        float2 a0 = bf2f(vA.x), a1 = bf2f(vA.y), a2 = bf2f(vA.z), a3 = bf2f(vA.w);
        float2 b0 = bf2f(vB.x), b1 = bf2f(vB.y), b2 = bf2f(vB.z), b3 = bf2f(vB.w);
        s0 += a0.x + b0.x; s1 += a0.y + b0.y;
        s2 += a1.x + b1.x; s3 += a1.y + b1.y;
        s4 += a2.x + b2.x; s5 += a2.y + b2.y;
        s6 += a3.x + b3.x; s7 += a3.y + b3.y;
    }
    if (e < end) {
        int sA = g_esrc[e];
        uint4 vA = *(const uint4*)(P + (size_t)sA * 128 + sub * 8);
        float2 a0 = bf2f(vA.x), a1 = bf2f(vA.y), a2 = bf2f(vA.z), a3 = bf2f(vA.w);
        s0 += a0.x; s1 += a0.y; s2 += a1.x; s3 += a1.y;
        s4 += a2.x; s5 += a2.y; s6 += a3.x; s7 += a3.y;
    }
    // add lo-plane partial (lanes 16-31) into hi lanes (0-15)
    s0 += __shfl_down_sync(0xffffffffu, s0, 16);
    s1 += __shfl_down_sync(0xffffffffu, s1, 16);
    s2 += __shfl_down_sync(0xffffffffu, s2, 16);
    s3 += __shfl_down_sync(0xffffffffu, s3, 16);
    s4 += __shfl_down_sync(0xffffffffu, s4, 16);
    s5 += __shfl_down_sync(0xffffffffu, s5, 16);
    s6 += __shfl_down_sync(0xffffffffu, s6, 16);
    s7 += __shfl_down_sync(0xffffffffu, s7, 16);
    if (lane < 16) {
        float inv = g_invdeg[node];
        uint4 hp, lp;
        hp.x = cvt2(s0 * inv, s1 * inv, lp.x);
        hp.y = cvt2(s2 * inv, s3 * inv, lp.y);
        hp.z = cvt2(s4 * inv, s5 * inv, lp.z);
        hp.w = cvt2(s6 * inv, s7 * inv, lp.w);
        size_t o = (size_t)node * 128 + sub * 8;
        *(uint4*)(g_pagg + o) = hp;
        *(uint4*)(g_pagg + (size_t)MAXN * 128 + o) = lp;
    }
}

// ---------------- tensor-core fused GEMM (+ optional scan CTA) --------------
// If doScan: blockIdx 0 runs the CSR exclusive scan (hidden under the GEMM);
// GEMM tiles use blockIdx - doScan. Scan also zeroes g_cursor.
// GEMM: acc = sum_k A[m][k]*W[n][k]; v = relu(bn(acc + bias)) (+resid planes)
// A as bf16 hi/lo planes; if A2hi, chunks 4..7 (k>=128) from A2 (pitch 128).
// 8 chunks of BK=32, 3-stage cp.async pipeline, 1 sync/chunk.
// SMEM tile row = [32 bf16 hi | 32 bf16 lo] = 128B, SW128-swizzled.
#define SM_STG  32768
#define SM_T0   2048
#define SM_TOTAL (2048 + 3 * 32768)

__global__ void __launch_bounds__(256, 2)
k_gemm_tc(const __nv_bfloat16* __restrict__ Ahi, const __nv_bfloat16* __restrict__ Alo,
          int pitchA,
          const __nv_bfloat16* __restrict__ A2hi, const __nv_bfloat16* __restrict__ A2lo,
          const __nv_bfloat16* __restrict__ WHI, const __nv_bfloat16* __restrict__ WLO,
          const float* __restrict__ bias,
          const float* __restrict__ gamma, const float* __restrict__ beta,
          const float* __restrict__ mean, const float* __restrict__ var,
          const __nv_bfloat16* __restrict__ RHI, const __nv_bfloat16* __restrict__ RLO,
          float* __restrict__ out,
          __nv_bfloat16* __restrict__ PHI, __nv_bfloat16* __restrict__ PLO, int N,
          int doScan)
{
    int tid = threadIdx.x;
    int tile = (int)blockIdx.x - doScan;
    if (tile < 0) {
        // ---- CSR exclusive scan over degrees (256 threads) + cursor zero ----
        __shared__ int s[256];
        int chunk = (N + 255) >> 8;
        int b0 = tid * chunk, b1 = min(N, b0 + chunk);
        int loc = 0;
        for (int i = b0; i < b1; i++) loc += g_deg[i];
        s[tid] = loc;
        __syncthreads();
        for (int off = 1; off < 256; off <<= 1) {
            int v = (tid >= off) ? s[tid - off] : 0;
            __syncthreads();
            s[tid] += v;
            __syncthreads();
        }
        int run = s[tid] - loc;
        for (int i = b0; i < b1; i++) {
            g_off[i] = run;
            int d = g_deg[i];
            run += d;
            g_invdeg[i] = 1.0f / (float)max(d, 1);
            g_cursor[i] = 0;
        }
        if (tid == 255) g_off[N] = s[255];
        return;
    }

    extern __shared__ char sm[];
    uint32_t smem_base = smem_to_u32(sm);
    int wid  = tid >> 5;
    int lane = tid & 31;
    int wm   = wid & 3;
    int wn   = wid >> 2;
    int rowBase = tile * 128;

    float* p_bs = (float*)(sm + 128);
    float* p_sc = (float*)(sm + 640);
    float* p_sh = (float*)(sm + 1152);
    if (tid < 128) {
        float s = gamma[tid] * rsqrtf(var[tid] + 1e-5f);
        p_sc[tid] = s;
        p_sh[tid] = beta[tid] - mean[tid] * s;
        p_bs[tid] = bias[tid];
    }

    // per-thread copy constants: 4 16B units each for A and B per stage
    int rowl  = tid >> 3;              // 0..31 (+ i*32)
    int c16   = tid & 7;               // 16B column within 128B row
    int half  = c16 >> 2;              // 0=hi, 1=lo
    int kelem = (c16 & 3) * 8;         // bf16 elem offset within 32-elem chunk
    const __nv_bfloat16* pA  = half ? Alo  : Ahi;
    const __nv_bfloat16* pA2 = half ? A2lo : A2hi;
    const __nv_bfloat16* pW  = half ? WLO  : WHI;

    auto copy_stage = [&](int c, int s) {
        bool use2 = (A2hi != nullptr) && (c >= 4);
        const __nv_bfloat16* pa = use2 ? pA2 : pA;
        int pit  = use2 ? 128 : pitchA;
        int kofA = (use2 ? (c * 32 - 128) : (c * 32)) + kelem;
        int kofB = c * 32 + kelem;
        uint32_t abase = smem_base + SM_T0 + s * SM_STG;
        uint32_t bbase = abase + 16384;
#pragma unroll
        for (int i = 0; i < 4; i++) {
            int row = rowl + i * 32;
            int gr = rowBase + row;
            int grs = min(gr, N - 1);
            uint32_t so = SWZ(row * 128 + c16 * 16);
            cp16(abase + so, pa + (size_t)grs * pit + kofA, (gr < N) ? 16 : 0);
            cp16(bbase + so, pW + (size_t)row * 256 + kofB, 16);
        }
        asm volatile("cp.async.commit_group;");
    };

    // ldmatrix per-thread offsets
    int laA[2];
#pragma unroll
    for (int mt = 0; mt < 2; mt++)
        laA[mt] = (wm * 32 + mt * 16 + (lane & 15)) * 128 + ((lane >> 4) * 16);
    int lbB[4];
#pragma unroll
    for (int np = 0; np < 4; np++)
        lbB[np] = (wn * 64 + np * 16 + ((lane >> 4) * 8) + (lane & 7)) * 128
                  + (((lane >> 3) & 1) * 16);

    float acc[2][8][4];
#pragma unroll
    for (int mt = 0; mt < 2; mt++)
#pragma unroll
        for (int nt = 0; nt < 8; nt++)
#pragma unroll
            for (int q = 0; q < 4; q++) acc[mt][nt][q] = 0.f;

    copy_stage(0, 0);
    copy_stage(1, 1);

    for (int c = 0; c < 8; c++) {
        if (c < 7) asm volatile("cp.async.wait_group 1;");
        else       asm volatile("cp.async.wait_group 0;");
        __syncthreads();                 // stage c visible; stage (c-1) compute done by all
        if (c + 2 < 8) copy_stage(c + 2, (c + 2) % 3);

        int buf = c % 3;
        uint32_t abase = smem_base + SM_T0 + buf * SM_STG;
        uint32_t bbase = abase + 16384;
#pragma unroll
        for (int ks = 0; ks < 2; ks++) {
            uint32_t ah[2][4], al[2][4];
#pragma unroll
            for (int mt = 0; mt < 2; mt++) {
                ldsm4(ah[mt], abase + SWZ(laA[mt] + ks * 32));
                ldsm4(al[mt], abase + SWZ(laA[mt] + 64 + ks * 32));
            }
#pragma unroll
            for (int np = 0; np < 4; np++) {
                uint32_t bh[4], bl[4];
                ldsm4(bh, bbase + SWZ(lbB[np] + ks * 32));
                ldsm4(bl, bbase + SWZ(lbB[np] + 64 + ks * 32));
#pragma unroll
                for (int mt = 0; mt < 2; mt++) {
                    mma16816(acc[mt][np * 2],     ah[mt], bh[0], bh[1]);   // hi*hi
                    mma16816(acc[mt][np * 2 + 1], ah[mt], bh[2], bh[3]);
                    mma16816(acc[mt][np * 2],     ah[mt], bl[0], bl[1]);   // hi*lo
                    mma16816(acc[mt][np * 2 + 1], ah[mt], bl[2], bl[3]);
                    mma16816(acc[mt][np * 2],     al[mt], bh[0], bh[1]);   // lo*hi
                    mma16816(acc[mt][np * 2 + 1], al[mt], bh[2], bh[3]);
                }
            }
        }
    }

    // ---- epilogue: bias -> BN -> ReLU -> (+resid from planes) -> outputs ----
    int tg   = lane >> 2;
    int tid4 = lane & 3;
#pragma unroll
    for (int nt = 0; nt < 8; nt++) {
        int cc = wn * 64 + nt * 8 + tid4 * 2;
        float s0 = p_sc[cc], s1 = p_sc[cc + 1];
        float h0v = p_sh[cc], h1v = p_sh[cc + 1];
        float b0v = p_bs[cc], b1v = p_bs[cc + 1];
#pragma unroll
        for (int mt = 0; mt < 2; mt++) {
            int r0 = rowBase + wm * 32 + mt * 16 + tg;
            int r1 = r0 + 8;
            float v00 = fmaxf((acc[mt][nt][0] + b0v) * s0 + h0v, 0.f);
            float v01 = fmaxf((acc[mt][nt][1] + b1v) * s1 + h1v, 0.f);
            float v10 = fmaxf((acc[mt][nt][2] + b0v) * s0 + h0v, 0.f);
            float v11 = fmaxf((acc[mt][nt][3] + b1v) * s1 + h1v, 0.f);
            if (RHI) {
                if (r0 < N) {
                    float2 rh = bf2f(*(const uint32_t*)(RHI + (size_t)r0 * 128 + cc));
                    float2 rl = bf2f(*(const uint32_t*)(RLO + (size_t)r0 * 128 + cc));
                    v00 += rh.x + rl.x; v01 += rh.y + rl.y;
                }
                if (r1 < N) {
                    float2 rh = bf2f(*(const uint32_t*)(RHI + (size_t)r1 * 128 + cc));
                    float2 rl = bf2f(*(const uint32_t*)(RLO + (size_t)r1 * 128 + cc));
                    v10 += rh.x + rl.x; v11 += rh.y + rl.y;
                }
            }
            if (r0 < N) {
                if (out) *(float2*)(out + (size_t)r0 * 128 + cc) = make_float2(v00, v01);
                if (PHI) {
                    uint32_t lo, hi = cvt2(v00, v01, lo);
                    *(uint32_t*)(PHI + (size_t)r0 * 128 + cc) = hi;
                    *(uint32_t*)(PLO + (size_t)r0 * 128 + cc) = lo;
                }
            }
            if (r1 < N) {
                if (out) *(float2*)(out + (size_t)r1 * 128 + cc) = make_float2(v10, v11);
                if (PHI) {
                    uint32_t lo, hi = cvt2(v10, v11, lo);
                    *(uint32_t*)(PHI + (size_t)r1 * 128 + cc) = hi;
                    *(uint32_t*)(PLO + (size_t)r1 * 128 + cc) = lo;
                }
            }
        }
    }
}

// ---------------- launch ----------------------------------------------------
extern "C" void kernel_launch(void* const* d_in, const int* in_sizes, int n_in,
                              void* d_out, int out_size) {
    const float* x    = (const float*)d_in[0];
    const int*   ei   = (const int*)  d_in[1];
    const float* W_in = (const float*)d_in[2];
    const float* b_in = (const float*)d_in[3];
    const float* big  = (const float*)d_in[4];
    const float* bib  = (const float*)d_in[5];
    const float* bim  = (const float*)d_in[6];
    const float* biv  = (const float*)d_in[7];
    const float* Wl   = (const float*)d_in[8];
    const float* bl   = (const float*)d_in[9];
    const float* Wr   = (const float*)d_in[10];
    const float* bg   = (const float*)d_in[11];
    const float* bb   = (const float*)d_in[12];
    const float* bm   = (const float*)d_in[13];
    const float* bv   = (const float*)d_in[14];

    int N = in_sizes[0] / 256;
    int E = in_sizes[1] / 2;
    const int* src = ei;
    const int* dst = ei + E;
    float* out = (float*)d_out;

    __nv_bfloat16 *whi, *wlo, *px, *ph, *pagg;
    int *degp;
    cudaGetSymbolAddress((void**)&whi,  g_wthi);
    cudaGetSymbolAddress((void**)&wlo,  g_wtlo);
    cudaGetSymbolAddress((void**)&px,   g_px);
    cudaGetSymbolAddress((void**)&ph,   g_ph);
    cudaGetSymbolAddress((void**)&pagg, g_pagg);
    cudaGetSymbolAddress((void**)&degp, g_deg);

    cudaFuncSetAttribute(k_gemm_tc, cudaFuncAttributeMaxDynamicSharedMemorySize, SM_TOTAL);

    const size_t PXL = (size_t)MAXN * 256;   // x lo-plane offset
    const size_t PHL = (size_t)MAXN * 128;   // h/agg lo-plane offset

    // zero degrees (capturable memset node)
    cudaMemsetAsync(degp, 0, (size_t)N * sizeof(int));

    int nf4 = N * 64;
    int nbA = (nf4 + 255) / 256;             // x-split blocks
    int nbB = (E + 255) / 256;               // count blocks
    int nbC = (4 * 128 * 256 + 255) / 256;   // prep blocks
    // block-partitioned prologue: split | count | prep run concurrently
    k_pro<<<nbA + nbB + nbC, 256>>>(x, dst, W_in, Wl, Wr, nf4, E, nbA, nbB);

    int gblocks = (N + 127) / 128;

    // input projection (x planes, pitch 256 -> h planes) + scan CTA (block 0)
    k_gemm_tc<<<gblocks + 1, 256, SM_TOTAL>>>(
        px, px + PXL, 256, nullptr, nullptr,
        whi, wlo, b_in, big, bib, bim, biv,
        nullptr, nullptr, nullptr, ph, ph + PHL, N, 1);

    // CSR fill (needs scan done — guaranteed by kernel ordering)
    k_fill<<<(E + 255) / 256, 256>>>(src, dst, E);

    // h-plane ping-pong: hcur = {ph, px(pong), ph}; dest = {px(pong), ph, fp32 out}
    __nv_bfloat16* hcur[3] = { ph, px, ph };
    __nv_bfloat16* pdst[3] = { px, ph, nullptr };
    for (int l = 0; l < 3; l++) {
        k_gather<<<((size_t)N * 32 + 255) / 256, 256>>>(hcur[l], hcur[l] + PHL, N);
        k_gemm_tc<<<gblocks, 256, SM_TOTAL>>>(pagg, pagg + PHL, 128,
                                              hcur[l], hcur[l] + PHL,
                                              whi + (size_t)(l + 1) * 128 * 256,
                                              wlo + (size_t)(l + 1) * 128 * 256,
                                              bl + l * 128, bg + l * 128, bb + l * 128,
                                              bm + l * 128, bv + l * 128,
                                              hcur[l], hcur[l] + PHL,
                                              (l == 2) ? out : nullptr,
                                              pdst[l], pdst[l] ? pdst[l] + PHL : nullptr, N,
                                              0);
    }
}

// round 15
// speedup vs baseline: 1.0507x; 1.0507x over previous
#include <cuda_runtime.h>
#include <cuda_bf16.h>
#include <cstdint>
#include <cstddef>

#define MAXN 100000
#define MAXE 640000
#define DD   128

// ---------------- scratch (static device globals; no allocation) ------------
__device__ int   g_deg[MAXN];
__device__ int   g_cursor[MAXN];
__device__ int   g_off[MAXN + 1];
__device__ int   g_esrc[MAXE];
__device__ float g_invdeg[MAXN];
__device__ __nv_bfloat16 g_wthi[4 * 128 * 256];      // weights [mat][n][k], bf16 hi
__device__ __nv_bfloat16 g_wtlo[4 * 128 * 256];      // weights [mat][n][k], bf16 lo
// bf16 hi/lo planes:
__device__ __nv_bfloat16 g_px[(size_t)2 * MAXN * 256];   // x planes; later reused as h-pong (pitch 128)
__device__ __nv_bfloat16 g_ph[(size_t)2 * MAXN * 128];   // h planes ping
__device__ __nv_bfloat16 g_pagg[(size_t)2 * MAXN * 128]; // agg planes

// ---------------- helpers ---------------------------------------------------
__device__ __forceinline__ uint32_t smem_to_u32(const void* p) {
    uint32_t a;
    asm("{ .reg .u64 t; cvta.to.shared.u64 t, %1; cvt.u32.u64 %0, t; }" : "=r"(a) : "l"(p));
    return a;
}
#define SWZ(o) ((o) ^ (((o) >> 3) & 0x70))

__device__ __forceinline__ uint32_t cvt2(float a, float b, uint32_t& lo_out) {
    __nv_bfloat16 ha = __float2bfloat16(a), hb = __float2bfloat16(b);
    __nv_bfloat16 la = __float2bfloat16(a - __bfloat162float(ha));
    __nv_bfloat16 lb = __float2bfloat16(b - __bfloat162float(hb));
    lo_out = (uint32_t)__bfloat16_as_ushort(la) | ((uint32_t)__bfloat16_as_ushort(lb) << 16);
    return (uint32_t)__bfloat16_as_ushort(ha) | ((uint32_t)__bfloat16_as_ushort(hb) << 16);
}
__device__ __forceinline__ float2 bf2f(uint32_t u) {
    __nv_bfloat162 b;
    *reinterpret_cast<uint32_t*>(&b) = u;
    return __bfloat1622float2(b);
}
__device__ __forceinline__ void ldsm4(uint32_t* r, uint32_t addr) {
    asm volatile("ldmatrix.sync.aligned.m8n8.x4.shared.b16 {%0,%1,%2,%3}, [%4];"
                 : "=r"(r[0]), "=r"(r[1]), "=r"(r[2]), "=r"(r[3]) : "r"(addr));
}
__device__ __forceinline__ void mma16816(float* d, const uint32_t* a,
                                         uint32_t b0, uint32_t b1) {
    asm volatile(
        "mma.sync.aligned.m16n8k16.row.col.f32.bf16.bf16.f32 "
        "{%0,%1,%2,%3}, {%4,%5,%6,%7}, {%8,%9}, {%0,%1,%2,%3};"
        : "+f"(d[0]), "+f"(d[1]), "+f"(d[2]), "+f"(d[3])
        : "r"(a[0]), "r"(a[1]), "r"(a[2]), "r"(a[3]), "r"(b0), "r"(b1));
}
__device__ __forceinline__ void cp16(uint32_t dst, const void* src, int sz) {
    asm volatile("cp.async.cg.shared.global [%0], [%1], 16, %2;"
                 :: "r"(dst), "l"(src), "r"(sz));
}

// -------- block-partitioned prologue: x split | degree count | weight prep --
// g_deg pre-zeroed via cudaMemsetAsync. Each block runs exactly one path
// (block-uniform branch; per-path register footprints stay independent).
__global__ void k_pro(const float* __restrict__ x, const int* __restrict__ dst,
                      const float* __restrict__ W_in, const float* __restrict__ Wl,
                      const float* __restrict__ Wr,
                      int nf4, int E, int nbA, int nbB) {
    int b = blockIdx.x;
    if (b < nbA) {
        int u = b * 256 + threadIdx.x;
        if (u < nf4) {
            float4 f = ((const float4*)x)[u];
            uint32_t lo0, lo1;
            uint32_t hi0 = cvt2(f.x, f.y, lo0);
            uint32_t hi1 = cvt2(f.z, f.w, lo1);
            ((uint2*)g_px)[u] = make_uint2(hi0, hi1);
            ((uint2*)(g_px + (size_t)MAXN * 256))[u] = make_uint2(lo0, lo1);
        }
    } else if (b < nbA + nbB) {
        int e = (b - nbA) * 256 + threadIdx.x;
        if (e < E) atomicAdd(&g_deg[dst[e]], 1);
    } else {
        int u = (b - nbA - nbB) * 256 + threadIdx.x;
        if (u < 4 * 128 * 256) {
            int m = u >> 15;
            int n = (u >> 8) & 127;
            int k = u & 255;
            float v;
            if (m == 0) v = W_in[(size_t)k * 128 + n];
            else {
                int l = m - 1;
                v = (k < 128) ? Wl[((size_t)l * 128 + k) * 128 + n]
                              : Wr[((size_t)l * 128 + (k - 128)) * 128 + n];
            }
            __nv_bfloat16 hi = __float2bfloat16(v);
            g_wthi[u] = hi;
            g_wtlo[u] = __float2bfloat16(v - __bfloat162float(hi));
        }
    }
}

// ------------- CSR exclusive scan (also zeroes cursor) ----------------------
__global__ void k_scan(int N) {
    __shared__ int s[1024];
    int t = threadIdx.x;
    int chunk = (N + 1023) >> 10;
    int b0 = t * chunk, b1 = min(N, b0 + chunk);
    int loc = 0;
    for (int i = b0; i < b1; i++) loc += g_deg[i];
    s[t] = loc;
    __syncthreads();
    for (int off = 1; off < 1024; off <<= 1) {
        int v = (t >= off) ? s[t - off] : 0;
        __syncthreads();
        s[t] += v;
        __syncthreads();
    }
    int run = s[t] - loc;
    for (int i = b0; i < b1; i++) {
        g_off[i] = run;
        int d = g_deg[i];
        run += d;
        g_invdeg[i] = 1.0f / (float)max(d, 1);
        g_cursor[i] = 0;
    }
    if (t == 1023) g_off[N] = s[1023];
}

__global__ void k_fill(const int* __restrict__ src, const int* __restrict__ dst, int E) {
    int e = blockIdx.x * blockDim.x + threadIdx.x;
    if (e < E) {
        int d = dst[e];
        int p = atomicAdd(&g_cursor[d], 1);
        g_esrc[g_off[d] + p] = src[e];
    }
}

// -------- mean aggregation: gather from h planes -> agg planes --------------
// Full warp per node; each lane owns 4 dims, loads uint2 hi + uint2 lo.
__global__ void k_gather(const __nv_bfloat16* __restrict__ HHI,
                         const __nv_bfloat16* __restrict__ HLO, int N) {
    int gtid = blockIdx.x * blockDim.x + threadIdx.x;
    int node = gtid >> 5;
    int lane = gtid & 31;
    if (node >= N) return;
    int beg = g_off[node], end = g_off[node + 1];
    float sx = 0.f, sy = 0.f, sz = 0.f, sw = 0.f;
    for (int e = beg; e < end; e++) {
        int s = g_esrc[e];
        size_t o = (size_t)s * 128 + lane * 4;
        uint2 hv = *(const uint2*)(HHI + o);
        uint2 lv = *(const uint2*)(HLO + o);
        float2 h0 = bf2f(hv.x), h1 = bf2f(hv.y);
        float2 l0 = bf2f(lv.x), l1 = bf2f(lv.y);
        sx += h0.x + l0.x; sy += h0.y + l0.y;
        sz += h1.x + l1.x; sw += h1.y + l1.y;
    }
    float inv = g_invdeg[node];
    uint32_t lo0, lo1;
    uint32_t hi0 = cvt2(sx * inv, sy * inv, lo0);
    uint32_t hi1 = cvt2(sz * inv, sw * inv, lo1);
    size_t o = ((size_t)node * 128 + lane * 4) >> 2;   // uint2 index
    ((uint2*)g_pagg)[o] = make_uint2(hi0, hi1);
    ((uint2*)(g_pagg + (size_t)MAXN * 128))[o] = make_uint2(lo0, lo1);
}

// ---------------- tensor-core fused GEMM ------------------------------------
// acc = sum_k A[m][k]*W[n][k]; v = relu(bn(acc + bias)) (+ resid from planes)
// Outputs: fp32 'out' (if non-null) and/or bf16 hi/lo planes PHI/PLO.
// A as bf16 hi/lo planes. If A2hi: chunks 4..7 (k>=128) come from A2 planes
// (pitch 128). 8 chunks of BK=32, 3-stage cp.async pipeline, 1 sync/chunk.
// SMEM tile row = [32 bf16 hi | 32 bf16 lo] = 128B, SW128-swizzled.
#define SM_STG  32768
#define SM_T0   2048
#define SM_TOTAL (2048 + 3 * 32768)

__global__ void __launch_bounds__(256, 2)
k_gemm_tc(const __nv_bfloat16* __restrict__ Ahi, const __nv_bfloat16* __restrict__ Alo,
          int pitchA,
          const __nv_bfloat16* __restrict__ A2hi, const __nv_bfloat16* __restrict__ A2lo,
          const __nv_bfloat16* __restrict__ WHI, const __nv_bfloat16* __restrict__ WLO,
          const float* __restrict__ bias,
          const float* __restrict__ gamma, const float* __restrict__ beta,
          const float* __restrict__ mean, const float* __restrict__ var,
          const __nv_bfloat16* __restrict__ RHI, const __nv_bfloat16* __restrict__ RLO,
          float* __restrict__ out,
          __nv_bfloat16* __restrict__ PHI, __nv_bfloat16* __restrict__ PLO, int N)
{
    extern __shared__ char sm[];
    uint32_t smem_base = smem_to_u32(sm);
    int tid  = threadIdx.x;
    int wid  = tid >> 5;
    int lane = tid & 31;
    int wm   = wid & 3;
    int wn   = wid >> 2;
    int rowBase = blockIdx.x * 128;

    float* p_bs = (float*)(sm + 128);
    float* p_sc = (float*)(sm + 640);
    float* p_sh = (float*)(sm + 1152);
    if (tid < 128) {
        float s = gamma[tid] * rsqrtf(var[tid] + 1e-5f);
        p_sc[tid] = s;
        p_sh[tid] = beta[tid] - mean[tid] * s;
        p_bs[tid] = bias[tid];
    }

    // per-thread copy constants: 4 16B units each for A and B per stage
    int rowl  = tid >> 3;              // 0..31 (+ i*32)
    int c16   = tid & 7;               // 16B column within 128B row
    int half  = c16 >> 2;              // 0=hi, 1=lo
    int kelem = (c16 & 3) * 8;         // bf16 elem offset within 32-elem chunk
    const __nv_bfloat16* pA  = half ? Alo  : Ahi;
    const __nv_bfloat16* pA2 = half ? A2lo : A2hi;
    const __nv_bfloat16* pW  = half ? WLO  : WHI;

    auto copy_stage = [&](int c, int s) {
        bool use2 = (A2hi != nullptr) && (c >= 4);
        const __nv_bfloat16* pa = use2 ? pA2 : pA;
        int pit  = use2 ? 128 : pitchA;
        int kofA = (use2 ? (c * 32 - 128) : (c * 32)) + kelem;
        int kofB = c * 32 + kelem;
        uint32_t abase = smem_base + SM_T0 + s * SM_STG;
        uint32_t bbase = abase + 16384;
#pragma unroll
        for (int i = 0; i < 4; i++) {
            int row = rowl + i * 32;
            int gr = rowBase + row;
            int grs = min(gr, N - 1);
            uint32_t so = SWZ(row * 128 + c16 * 16);
            cp16(abase + so, pa + (size_t)grs * pit + kofA, (gr < N) ? 16 : 0);
            cp16(bbase + so, pW + (size_t)row * 256 + kofB, 16);
        }
        asm volatile("cp.async.commit_group;");
    };

    // ldmatrix per-thread offsets
    int laA[2];
#pragma unroll
    for (int mt = 0; mt < 2; mt++)
        laA[mt] = (wm * 32 + mt * 16 + (lane & 15)) * 128 + ((lane >> 4) * 16);
    int lbB[4];
#pragma unroll
    for (int np = 0; np < 4; np++)
        lbB[np] = (wn * 64 + np * 16 + ((lane >> 4) * 8) + (lane & 7)) * 128
                  + (((lane >> 3) & 1) * 16);

    float acc[2][8][4];
#pragma unroll
    for (int mt = 0; mt < 2; mt++)
#pragma unroll
        for (int nt = 0; nt < 8; nt++)
#pragma unroll
            for (int q = 0; q < 4; q++) acc[mt][nt][q] = 0.f;

    copy_stage(0, 0);
    copy_stage(1, 1);

    for (int c = 0; c < 8; c++) {
        if (c < 7) asm volatile("cp.async.wait_group 1;");
        else       asm volatile("cp.async.wait_group 0;");
        __syncthreads();                 // stage c visible; stage (c-1) compute done by all
        if (c + 2 < 8) copy_stage(c + 2, (c + 2) % 3);

        int buf = c % 3;
        uint32_t abase = smem_base + SM_T0 + buf * SM_STG;
        uint32_t bbase = abase + 16384;
#pragma unroll
        for (int ks = 0; ks < 2; ks++) {
            uint32_t ah[2][4], al[2][4];
#pragma unroll
            for (int mt = 0; mt < 2; mt++) {
                ldsm4(ah[mt], abase + SWZ(laA[mt] + ks * 32));
                ldsm4(al[mt], abase + SWZ(laA[mt] + 64 + ks * 32));
            }
#pragma unroll
            for (int np = 0; np < 4; np++) {
                uint32_t bh[4], bl[4];
                ldsm4(bh, bbase + SWZ(lbB[np] + ks * 32));
                ldsm4(bl, bbase + SWZ(lbB[np] + 64 + ks * 32));
#pragma unroll
                for (int mt = 0; mt < 2; mt++) {
                    mma16816(acc[mt][np * 2],     ah[mt], bh[0], bh[1]);   // hi*hi
                    mma16816(acc[mt][np * 2 + 1], ah[mt], bh[2], bh[3]);
                    mma16816(acc[mt][np * 2],     ah[mt], bl[0], bl[1]);   // hi*lo
                    mma16816(acc[mt][np * 2 + 1], ah[mt], bl[2], bl[3]);
                    mma16816(acc[mt][np * 2],     al[mt], bh[0], bh[1]);   // lo*hi
                    mma16816(acc[mt][np * 2 + 1], al[mt], bh[2], bh[3]);
                }
            }
        }
    }

    // ---- epilogue: bias -> BN -> ReLU -> (+resid from planes) -> outputs ----
    int tg   = lane >> 2;
    int tid4 = lane & 3;
#pragma unroll
    for (int nt = 0; nt < 8; nt++) {
        int cc = wn * 64 + nt * 8 + tid4 * 2;
        float s0 = p_sc[cc], s1 = p_sc[cc + 1];
        float h0v = p_sh[cc], h1v = p_sh[cc + 1];
        float b0v = p_bs[cc], b1v = p_bs[cc + 1];
#pragma unroll
        for (int mt = 0; mt < 2; mt++) {
            int r0 = rowBase + wm * 32 + mt * 16 + tg;
            int r1 = r0 + 8;
            float v00 = fmaxf((acc[mt][nt][0] + b0v) * s0 + h0v, 0.f);
            float v01 = fmaxf((acc[mt][nt][1] + b1v) * s1 + h1v, 0.f);
            float v10 = fmaxf((acc[mt][nt][2] + b0v) * s0 + h0v, 0.f);
            float v11 = fmaxf((acc[mt][nt][3] + b1v) * s1 + h1v, 0.f);
            if (RHI) {
                if (r0 < N) {
                    float2 rh = bf2f(*(const uint32_t*)(RHI + (size_t)r0 * 128 + cc));
                    float2 rl = bf2f(*(const uint32_t*)(RLO + (size_t)r0 * 128 + cc));
                    v00 += rh.x + rl.x; v01 += rh.y + rl.y;
                }
                if (r1 < N) {
                    float2 rh = bf2f(*(const uint32_t*)(RHI + (size_t)r1 * 128 + cc));
                    float2 rl = bf2f(*(const uint32_t*)(RLO + (size_t)r1 * 128 + cc));
                    v10 += rh.x + rl.x; v11 += rh.y + rl.y;
                }
            }
            if (r0 < N) {
                if (out) *(float2*)(out + (size_t)r0 * 128 + cc) = make_float2(v00, v01);
                if (PHI) {
                    uint32_t lo, hi = cvt2(v00, v01, lo);
                    *(uint32_t*)(PHI + (size_t)r0 * 128 + cc) = hi;
                    *(uint32_t*)(PLO + (size_t)r0 * 128 + cc) = lo;
                }
            }
            if (r1 < N) {
                if (out) *(float2*)(out + (size_t)r1 * 128 + cc) = make_float2(v10, v11);
                if (PHI) {
                    uint32_t lo, hi = cvt2(v10, v11, lo);
                    *(uint32_t*)(PHI + (size_t)r1 * 128 + cc) = hi;
                    *(uint32_t*)(PLO + (size_t)r1 * 128 + cc) = lo;
                }
            }
        }
    }
}

// ---------------- launch ----------------------------------------------------
extern "C" void kernel_launch(void* const* d_in, const int* in_sizes, int n_in,
                              void* d_out, int out_size) {
    const float* x    = (const float*)d_in[0];
    const int*   ei   = (const int*)  d_in[1];
    const float* W_in = (const float*)d_in[2];
    const float* b_in = (const float*)d_in[3];
    const float* big  = (const float*)d_in[4];
    const float* bib  = (const float*)d_in[5];
    const float* bim  = (const float*)d_in[6];
    const float* biv  = (const float*)d_in[7];
    const float* Wl   = (const float*)d_in[8];
    const float* bl   = (const float*)d_in[9];
    const float* Wr   = (const float*)d_in[10];
    const float* bg   = (const float*)d_in[11];
    const float* bb   = (const float*)d_in[12];
    const float* bm   = (const float*)d_in[13];
    const float* bv   = (const float*)d_in[14];

    int N = in_sizes[0] / 256;
    int E = in_sizes[1] / 2;
    const int* src = ei;
    const int* dst = ei + E;
    float* out = (float*)d_out;

    __nv_bfloat16 *whi, *wlo, *px, *ph, *pagg;
    int *degp;
    cudaGetSymbolAddress((void**)&whi,  g_wthi);
    cudaGetSymbolAddress((void**)&wlo,  g_wtlo);
    cudaGetSymbolAddress((void**)&px,   g_px);
    cudaGetSymbolAddress((void**)&ph,   g_ph);
    cudaGetSymbolAddress((void**)&pagg, g_pagg);
    cudaGetSymbolAddress((void**)&degp, g_deg);

    cudaFuncSetAttribute(k_gemm_tc, cudaFuncAttributeMaxDynamicSharedMemorySize, SM_TOTAL);

    const size_t PXL = (size_t)MAXN * 256;   // x lo-plane offset
    const size_t PHL = (size_t)MAXN * 128;   // h/agg lo-plane offset

    // zero degrees (capturable memset node)
    cudaMemsetAsync(degp, 0, (size_t)N * sizeof(int));

    int nf4 = N * 64;
    int nbA = (nf4 + 255) / 256;             // x-split blocks
    int nbB = (E + 255) / 256;               // count blocks
    int nbC = (4 * 128 * 256 + 255) / 256;   // prep blocks
    // launch 1: block-partitioned prologue (split | count | prep concurrent)
    k_pro<<<nbA + nbB + nbC, 256>>>(x, dst, W_in, Wl, Wr, nf4, E, nbA, nbB);
    // launch 2: scan (+ cursor zero)
    k_scan<<<1, 1024>>>(N);
    // launch 3: CSR fill
    k_fill<<<(E + 255) / 256, 256>>>(src, dst, E);

    int gblocks = (N + 127) / 128;

    // launch 4 (ncu-captured): input projection -> h planes
    k_gemm_tc<<<gblocks, 256, SM_TOTAL>>>(px, px + PXL, 256, nullptr, nullptr,
                                          whi, wlo, b_in, big, bib, bim, biv,
                                          nullptr, nullptr, nullptr, ph, ph + PHL, N);

    // h-plane ping-pong: hcur = {ph, px(pong), ph}; dest = {px(pong), ph, fp32 out}
    __nv_bfloat16* hcur[3] = { ph, px, ph };
    __nv_bfloat16* pdst[3] = { px, ph, nullptr };
    for (int l = 0; l < 3; l++) {
        k_gather<<<((size_t)N * 32 + 255) / 256, 256>>>(hcur[l], hcur[l] + PHL, N);
        k_gemm_tc<<<gblocks, 256, SM_TOTAL>>>(pagg, pagg + PHL, 128,
                                              hcur[l], hcur[l] + PHL,
                                              whi + (size_t)(l + 1) * 128 * 256,
                                              wlo + (size_t)(l + 1) * 128 * 256,
                                              bl + l * 128, bg + l * 128, bb + l * 128,
                                              bm + l * 128, bv + l * 128,
                                              hcur[l], hcur[l] + PHL,
                                              (l == 2) ? out : nullptr,
                                              pdst[l], pdst[l] ? pdst[l] + PHL : nullptr, N);
    }
}

// round 16
// speedup vs baseline: 1.1523x; 1.0967x over previous
#include <cuda_runtime.h>
#include <cuda_bf16.h>
#include <cstdint>
#include <cstddef>

#define MAXN 100000
#define MAXE 640000
#define DD   128

// ---------------- scratch (static device globals; no allocation) ------------
__device__ int   g_deg[MAXN];
__device__ int   g_cursor[MAXN];
__device__ int   g_off[MAXN + 1];
__device__ int   g_esrc[MAXE];
__device__ float g_invdeg[MAXN];
__device__ __nv_bfloat16 g_wthi[4 * 128 * 256];      // weights [mat][n][k], bf16 hi
__device__ __nv_bfloat16 g_wtlo[4 * 128 * 256];      // weights [mat][n][k], bf16 lo
// bf16 hi/lo planes:
__device__ __nv_bfloat16 g_px[(size_t)2 * MAXN * 256];   // x planes; later reused as h-pong (pitch 128)
__device__ __nv_bfloat16 g_ph[(size_t)2 * MAXN * 128];   // h planes ping
__device__ __nv_bfloat16 g_pagg[(size_t)2 * MAXN * 128]; // agg planes

// ---------------- helpers ---------------------------------------------------
__device__ __forceinline__ uint32_t smem_to_u32(const void* p) {
    uint32_t a;
    asm("{ .reg .u64 t; cvta.to.shared.u64 t, %1; cvt.u32.u64 %0, t; }" : "=r"(a) : "l"(p));
    return a;
}
#define SWZ(o) ((o) ^ (((o) >> 3) & 0x70))

__device__ __forceinline__ uint32_t cvt2(float a, float b, uint32_t& lo_out) {
    __nv_bfloat16 ha = __float2bfloat16(a), hb = __float2bfloat16(b);
    __nv_bfloat16 la = __float2bfloat16(a - __bfloat162float(ha));
    __nv_bfloat16 lb = __float2bfloat16(b - __bfloat162float(hb));
    lo_out = (uint32_t)__bfloat16_as_ushort(la) | ((uint32_t)__bfloat16_as_ushort(lb) << 16);
    return (uint32_t)__bfloat16_as_ushort(ha) | ((uint32_t)__bfloat16_as_ushort(hb) << 16);
}
__device__ __forceinline__ float2 bf2f(uint32_t u) {
    __nv_bfloat162 b;
    *reinterpret_cast<uint32_t*>(&b) = u;
    return __bfloat1622float2(b);
}
__device__ __forceinline__ void ldsm4(uint32_t* r, uint32_t addr) {
    asm volatile("ldmatrix.sync.aligned.m8n8.x4.shared.b16 {%0,%1,%2,%3}, [%4];"
                 : "=r"(r[0]), "=r"(r[1]), "=r"(r[2]), "=r"(r[3]) : "r"(addr));
}
__device__ __forceinline__ void mma16816(float* d, const uint32_t* a,
                                         uint32_t b0, uint32_t b1) {
    asm volatile(
        "mma.sync.aligned.m16n8k16.row.col.f32.bf16.bf16.f32 "
        "{%0,%1,%2,%3}, {%4,%5,%6,%7}, {%8,%9}, {%0,%1,%2,%3};"
        : "+f"(d[0]), "+f"(d[1]), "+f"(d[2]), "+f"(d[3])
        : "r"(a[0]), "r"(a[1]), "r"(a[2]), "r"(a[3]), "r"(b0), "r"(b1));
}
__device__ __forceinline__ void cp16(uint32_t dst, const void* src, int sz) {
    asm volatile("cp.async.cg.shared.global [%0], [%1], 16, %2;"
                 :: "r"(dst), "l"(src), "r"(sz));
}

// ---------------- CSR build + x split ---------------------------------------
__global__ void k_init(const float* __restrict__ x, int nf4, int N) {
    int u = blockIdx.x * blockDim.x + threadIdx.x;
    if (u < N) { g_deg[u] = 0; g_cursor[u] = 0; }
    if (u < nf4) {
        float4 f = ((const float4*)x)[u];
        uint32_t lo0, lo1;
        uint32_t hi0 = cvt2(f.x, f.y, lo0);
        uint32_t hi1 = cvt2(f.z, f.w, lo1);
        ((uint2*)g_px)[u] = make_uint2(hi0, hi1);
        ((uint2*)(g_px + (size_t)MAXN * 256))[u] = make_uint2(lo0, lo1);
    }
}
__global__ void k_count(const int* __restrict__ dst, int E) {
    int e = blockIdx.x * blockDim.x + threadIdx.x;
    if (e < E) atomicAdd(&g_deg[dst[e]], 1);
}
__global__ void k_scan(int N) {
    __shared__ int s[1024];
    int t = threadIdx.x;
    int chunk = (N + 1023) >> 10;
    int b0 = t * chunk, b1 = min(N, b0 + chunk);
    int loc = 0;
    for (int i = b0; i < b1; i++) loc += g_deg[i];
    s[t] = loc;
    __syncthreads();
    for (int off = 1; off < 1024; off <<= 1) {
        int v = (t >= off) ? s[t - off] : 0;
        __syncthreads();
        s[t] += v;
        __syncthreads();
    }
    int run = s[t] - loc;
    for (int i = b0; i < b1; i++) {
        g_off[i] = run;
        int d = g_deg[i];
        run += d;
        g_invdeg[i] = 1.0f / (float)max(d, 1);
    }
    if (t == 1023) g_off[N] = s[1023];
}
__global__ void k_fill(const int* __restrict__ src, const int* __restrict__ dst, int E) {
    int e = blockIdx.x * blockDim.x + threadIdx.x;
    if (e < E) {
        int d = dst[e];
        int p = atomicAdd(&g_cursor[d], 1);
        g_esrc[g_off[d] + p] = src[e];
    }
}

// ------- weight transpose + bf16 hi/lo split: WT[m][n][k] = Wcat[k][n] ------
__global__ void k_prep(const float* __restrict__ W_in, const float* __restrict__ Wl,
                       const float* __restrict__ Wr) {
    int idx = blockIdx.x * blockDim.x + threadIdx.x;
    if (idx >= 4 * 128 * 256) return;
    int m = idx >> 15;
    int n = (idx >> 8) & 127;
    int k = idx & 255;
    float v;
    if (m == 0) v = W_in[(size_t)k * 128 + n];
    else {
        int l = m - 1;
        v = (k < 128) ? Wl[((size_t)l * 128 + k) * 128 + n]
                      : Wr[((size_t)l * 128 + (k - 128)) * 128 + n];
    }
    __nv_bfloat16 hi = __float2bfloat16(v);
    g_wthi[idx] = hi;
    g_wtlo[idx] = __float2bfloat16(v - __bfloat162float(hi));
}

// -------- mean aggregation: gather from h planes -> agg planes --------------
__global__ void k_gather(const __nv_bfloat16* __restrict__ HHI,
                         const __nv_bfloat16* __restrict__ HLO, int N) {
    int gtid = blockIdx.x * blockDim.x + threadIdx.x;
    int node = gtid >> 5;
    int lane = gtid & 31;
    if (node >= N) return;
    int beg = g_off[node], end = g_off[node + 1];
    float sx = 0.f, sy = 0.f, sz = 0.f, sw = 0.f;
    for (int e = beg; e < end; e++) {
        int s = g_esrc[e];
        size_t o = (size_t)s * 128 + lane * 4;
        uint2 hv = *(const uint2*)(HHI + o);
        uint2 lv = *(const uint2*)(HLO + o);
        float2 h0 = bf2f(hv.x), h1 = bf2f(hv.y);
        float2 l0 = bf2f(lv.x), l1 = bf2f(lv.y);
        sx += h0.x + l0.x; sy += h0.y + l0.y;
        sz += h1.x + l1.x; sw += h1.y + l1.y;
    }
    float inv = g_invdeg[node];
    uint32_t lo0, lo1;
    uint32_t hi0 = cvt2(sx * inv, sy * inv, lo0);
    uint32_t hi1 = cvt2(sz * inv, sw * inv, lo1);
    size_t o = ((size_t)node * 128 + lane * 4) >> 2;   // uint2 index
    ((uint2*)g_pagg)[o] = make_uint2(hi0, hi1);
    ((uint2*)(g_pagg + (size_t)MAXN * 128))[o] = make_uint2(lo0, lo1);
}

// ---------------- tensor-core fused GEMM ------------------------------------
// acc = sum_k A[m][k]*W[n][k]; v = relu(bn(acc + bias)) (+ resid from planes)
// Outputs: fp32 'out' (if non-null) and/or bf16 hi/lo planes PHI/PLO.
// A as bf16 hi/lo planes. If A2hi: chunks 4..7 (k>=128) come from A2 planes
// (pitch 128). 8 chunks of BK=32, 3-stage cp.async pipeline, 1 sync/chunk.
// SMEM tile row = [32 bf16 hi | 32 bf16 lo] = 128B, SW128-swizzled.
// Inner loop: B operands double-buffered so each np's ldmatrix latency hides
// behind the previous np's 12 MMAs.
#define SM_STG  32768
#define SM_T0   2048
#define SM_TOTAL (2048 + 3 * 32768)

__global__ void __launch_bounds__(256, 2)
k_gemm_tc(const __nv_bfloat16* __restrict__ Ahi, const __nv_bfloat16* __restrict__ Alo,
          int pitchA,
          const __nv_bfloat16* __restrict__ A2hi, const __nv_bfloat16* __restrict__ A2lo,
          const __nv_bfloat16* __restrict__ WHI, const __nv_bfloat16* __restrict__ WLO,
          const float* __restrict__ bias,
          const float* __restrict__ gamma, const float* __restrict__ beta,
          const float* __restrict__ mean, const float* __restrict__ var,
          const __nv_bfloat16* __restrict__ RHI, const __nv_bfloat16* __restrict__ RLO,
          float* __restrict__ out,
          __nv_bfloat16* __restrict__ PHI, __nv_bfloat16* __restrict__ PLO, int N)
{
    extern __shared__ char sm[];
    uint32_t smem_base = smem_to_u32(sm);
    int tid  = threadIdx.x;
    int wid  = tid >> 5;
    int lane = tid & 31;
    int wm   = wid & 3;
    int wn   = wid >> 2;
    int rowBase = blockIdx.x * 128;

    float* p_bs = (float*)(sm + 128);
    float* p_sc = (float*)(sm + 640);
    float* p_sh = (float*)(sm + 1152);
    if (tid < 128) {
        float s = gamma[tid] * rsqrtf(var[tid] + 1e-5f);
        p_sc[tid] = s;
        p_sh[tid] = beta[tid] - mean[tid] * s;
        p_bs[tid] = bias[tid];
    }

    // per-thread copy constants: 4 16B units each for A and B per stage
    int rowl  = tid >> 3;              // 0..31 (+ i*32)
    int c16   = tid & 7;               // 16B column within 128B row
    int half  = c16 >> 2;              // 0=hi, 1=lo
    int kelem = (c16 & 3) * 8;         // bf16 elem offset within 32-elem chunk
    const __nv_bfloat16* pA  = half ? Alo  : Ahi;
    const __nv_bfloat16* pA2 = half ? A2lo : A2hi;
    const __nv_bfloat16* pW  = half ? WLO  : WHI;

    auto copy_stage = [&](int c, int s) {
        bool use2 = (A2hi != nullptr) && (c >= 4);
        const __nv_bfloat16* pa = use2 ? pA2 : pA;
        int pit  = use2 ? 128 : pitchA;
        int kofA = (use2 ? (c * 32 - 128) : (c * 32)) + kelem;
        int kofB = c * 32 + kelem;
        uint32_t abase = smem_base + SM_T0 + s * SM_STG;
        uint32_t bbase = abase + 16384;
#pragma unroll
        for (int i = 0; i < 4; i++) {
            int row = rowl + i * 32;
            int gr = rowBase + row;
            int grs = min(gr, N - 1);
            uint32_t so = SWZ(row * 128 + c16 * 16);
            cp16(abase + so, pa + (size_t)grs * pit + kofA, (gr < N) ? 16 : 0);
            cp16(bbase + so, pW + (size_t)row * 256 + kofB, 16);
        }
        asm volatile("cp.async.commit_group;");
    };

    // ldmatrix per-thread offsets
    int laA[2];
#pragma unroll
    for (int mt = 0; mt < 2; mt++)
        laA[mt] = (wm * 32 + mt * 16 + (lane & 15)) * 128 + ((lane >> 4) * 16);
    int lbB[4];
#pragma unroll
    for (int np = 0; np < 4; np++)
        lbB[np] = (wn * 64 + np * 16 + ((lane >> 4) * 8) + (lane & 7)) * 128
                  + (((lane >> 3) & 1) * 16);

    float acc[2][8][4];
#pragma unroll
    for (int mt = 0; mt < 2; mt++)
#pragma unroll
        for (int nt = 0; nt < 8; nt++)
#pragma unroll
            for (int q = 0; q < 4; q++) acc[mt][nt][q] = 0.f;

    copy_stage(0, 0);
    copy_stage(1, 1);

    for (int c = 0; c < 8; c++) {
        if (c < 7) asm volatile("cp.async.wait_group 1;");
        else       asm volatile("cp.async.wait_group 0;");
        __syncthreads();                 // stage c visible; stage (c-1) compute done by all
        if (c + 2 < 8) copy_stage(c + 2, (c + 2) % 3);

        int buf = c % 3;
        uint32_t abase = smem_base + SM_T0 + buf * SM_STG;
        uint32_t bbase = abase + 16384;
#pragma unroll
        for (int ks = 0; ks < 2; ks++) {
            uint32_t ah[2][4], al[2][4];
#pragma unroll
            for (int mt = 0; mt < 2; mt++) {
                ldsm4(ah[mt], abase + SWZ(laA[mt] + ks * 32));
                ldsm4(al[mt], abase + SWZ(laA[mt] + 64 + ks * 32));
            }
            // B double buffer: prefetch np+1 while issuing MMAs for np
            uint32_t bh[2][4], bl[2][4];
            ldsm4(bh[0], bbase + SWZ(lbB[0] + ks * 32));
            ldsm4(bl[0], bbase + SWZ(lbB[0] + 64 + ks * 32));
#pragma unroll
            for (int np = 0; np < 4; np++) {
                int cur = np & 1, nx = cur ^ 1;
                if (np < 3) {
                    ldsm4(bh[nx], bbase + SWZ(lbB[np + 1] + ks * 32));
                    ldsm4(bl[nx], bbase + SWZ(lbB[np + 1] + 64 + ks * 32));
                }
#pragma unroll
                for (int mt = 0; mt < 2; mt++) {
                    mma16816(acc[mt][np * 2],     ah[mt], bh[cur][0], bh[cur][1]);   // hi*hi
                    mma16816(acc[mt][np * 2 + 1], ah[mt], bh[cur][2], bh[cur][3]);
                    mma16816(acc[mt][np * 2],     ah[mt], bl[cur][0], bl[cur][1]);   // hi*lo
                    mma16816(acc[mt][np * 2 + 1], ah[mt], bl[cur][2], bl[cur][3]);
                    mma16816(acc[mt][np * 2],     al[mt], bh[cur][0], bh[cur][1]);   // lo*hi
                    mma16816(acc[mt][np * 2 + 1], al[mt], bh[cur][2], bh[cur][3]);
                }
            }
        }
    }

    // ---- epilogue: bias -> BN -> ReLU -> (+resid from planes) -> outputs ----
    int tg   = lane >> 2;
    int tid4 = lane & 3;
#pragma unroll
    for (int nt = 0; nt < 8; nt++) {
        int cc = wn * 64 + nt * 8 + tid4 * 2;
        float s0 = p_sc[cc], s1 = p_sc[cc + 1];
        float h0v = p_sh[cc], h1v = p_sh[cc + 1];
        float b0v = p_bs[cc], b1v = p_bs[cc + 1];
#pragma unroll
        for (int mt = 0; mt < 2; mt++) {
            int r0 = rowBase + wm * 32 + mt * 16 + tg;
            int r1 = r0 + 8;
            float v00 = fmaxf((acc[mt][nt][0] + b0v) * s0 + h0v, 0.f);
            float v01 = fmaxf((acc[mt][nt][1] + b1v) * s1 + h1v, 0.f);
            float v10 = fmaxf((acc[mt][nt][2] + b0v) * s0 + h0v, 0.f);
            float v11 = fmaxf((acc[mt][nt][3] + b1v) * s1 + h1v, 0.f);
            if (RHI) {
                if (r0 < N) {
                    float2 rh = bf2f(*(const uint32_t*)(RHI + (size_t)r0 * 128 + cc));
                    float2 rl = bf2f(*(const uint32_t*)(RLO + (size_t)r0 * 128 + cc));
                    v00 += rh.x + rl.x; v01 += rh.y + rl.y;
                }
                if (r1 < N) {
                    float2 rh = bf2f(*(const uint32_t*)(RHI + (size_t)r1 * 128 + cc));
                    float2 rl = bf2f(*(const uint32_t*)(RLO + (size_t)r1 * 128 + cc));
                    v10 += rh.x + rl.x; v11 += rh.y + rl.y;
                }
            }
            if (r0 < N) {
                if (out) *(float2*)(out + (size_t)r0 * 128 + cc) = make_float2(v00, v01);
                if (PHI) {
                    uint32_t lo, hi = cvt2(v00, v01, lo);
                    *(uint32_t*)(PHI + (size_t)r0 * 128 + cc) = hi;
                    *(uint32_t*)(PLO + (size_t)r0 * 128 + cc) = lo;
                }
            }
            if (r1 < N) {
                if (out) *(float2*)(out + (size_t)r1 * 128 + cc) = make_float2(v10, v11);
                if (PHI) {
                    uint32_t lo, hi = cvt2(v10, v11, lo);
                    *(uint32_t*)(PHI + (size_t)r1 * 128 + cc) = hi;
                    *(uint32_t*)(PLO + (size_t)r1 * 128 + cc) = lo;
                }
            }
        }
    }
}

// ---------------- launch ----------------------------------------------------
extern "C" void kernel_launch(void* const* d_in, const int* in_sizes, int n_in,
                              void* d_out, int out_size) {
    const float* x    = (const float*)d_in[0];
    const int*   ei   = (const int*)  d_in[1];
    const float* W_in = (const float*)d_in[2];
    const float* b_in = (const float*)d_in[3];
    const float* big  = (const float*)d_in[4];
    const float* bib  = (const float*)d_in[5];
    const float* bim  = (const float*)d_in[6];
    const float* biv  = (const float*)d_in[7];
    const float* Wl   = (const float*)d_in[8];
    const float* bl   = (const float*)d_in[9];
    const float* Wr   = (const float*)d_in[10];
    const float* bg   = (const float*)d_in[11];
    const float* bb   = (const float*)d_in[12];
    const float* bm   = (const float*)d_in[13];
    const float* bv   = (const float*)d_in[14];

    int N = in_sizes[0] / 256;
    int E = in_sizes[1] / 2;
    const int* src = ei;
    const int* dst = ei + E;
    float* out = (float*)d_out;

    __nv_bfloat16 *whi, *wlo, *px, *ph, *pagg;
    cudaGetSymbolAddress((void**)&whi,  g_wthi);
    cudaGetSymbolAddress((void**)&wlo,  g_wtlo);
    cudaGetSymbolAddress((void**)&px,   g_px);
    cudaGetSymbolAddress((void**)&ph,   g_ph);
    cudaGetSymbolAddress((void**)&pagg, g_pagg);

    cudaFuncSetAttribute(k_gemm_tc, cudaFuncAttributeMaxDynamicSharedMemorySize, SM_TOTAL);

    const size_t PXL = (size_t)MAXN * 256;   // x lo-plane offset
    const size_t PHL = (size_t)MAXN * 128;   // h/agg lo-plane offset

    int nf4 = N * 64;
    k_init <<<(nf4 + 255) / 256, 256>>>(x, nf4, N);
    k_count<<<(E + 255) / 256, 256>>>(dst, E);
    k_scan <<<1, 1024>>>(N);
    k_fill <<<(E + 255) / 256, 256>>>(src, dst, E);
    k_prep <<<(4 * 128 * 256 + 255) / 256, 256>>>(W_in, Wl, Wr);

    int gblocks = (N + 127) / 128;

    // input projection: x planes (pitch 256) -> h planes in g_ph
    k_gemm_tc<<<gblocks, 256, SM_TOTAL>>>(px, px + PXL, 256, nullptr, nullptr,
                                          whi, wlo, b_in, big, bib, bim, biv,
                                          nullptr, nullptr, nullptr, ph, ph + PHL, N);

    // h-plane ping-pong: hcur = {ph, px(pong), ph}; dest = {px(pong), ph, fp32 out}
    __nv_bfloat16* hcur[3] = { ph, px, ph };
    __nv_bfloat16* pdst[3] = { px, ph, nullptr };
    for (int l = 0; l < 3; l++) {
        k_gather<<<((size_t)N * 32 + 255) / 256, 256>>>(hcur[l], hcur[l] + PHL, N);
        k_gemm_tc<<<gblocks, 256, SM_TOTAL>>>(pagg, pagg + PHL, 128,
                                              hcur[l], hcur[l] + PHL,
                                              whi + (size_t)(l + 1) * 128 * 256,
                                              wlo + (size_t)(l + 1) * 128 * 256,
                                              bl + l * 128, bg + l * 128, bb + l * 128,
                                              bm + l * 128, bv + l * 128,
                                              hcur[l], hcur[l] + PHL,
                                              (l == 2) ? out : nullptr,
                                              pdst[l], pdst[l] ? pdst[l] + PHL : nullptr, N);
    }
}